// round 1
// baseline (speedup 1.0000x reference)
#include <cuda_runtime.h>
#include <math.h>

// Problem dims (fixed by the dataset)
#define T_TOK 16384      // N*P = 4*4096 tokens
#define D_DIM 1024
#define H_DIM 4096
#define E_NUM 8

// Scratch (device globals: allocation-free rule)
__device__ float g_x[(size_t)T_TOK * D_DIM];        // LayerNorm output, 64 MB
__device__ float g_out[(size_t)T_TOK * H_DIM];      // expert-sum buffer, 256 MB
__device__ int   g_idx[E_NUM][T_TOK];               // per-expert token lists
__device__ int   g_cnt[E_NUM];

// ---------------------------------------------------------------------------
// Kernel 0: zero g_out and g_cnt (required every launch: graph replays)
// ---------------------------------------------------------------------------
__global__ void init_kernel() {
    size_t idx = (size_t)blockIdx.x * blockDim.x + threadIdx.x;
    const size_t n4 = (size_t)T_TOK * H_DIM / 4;
    float4 z = make_float4(0.f, 0.f, 0.f, 0.f);
    float4* p = reinterpret_cast<float4*>(g_out);
    size_t stride = (size_t)gridDim.x * blockDim.x;
    for (size_t i = idx; i < n4; i += stride) p[i] = z;
    if (idx < E_NUM) g_cnt[idx] = 0;
}

// ---------------------------------------------------------------------------
// Kernel 1: fused LayerNorm + gating (softmax skipped: top-k of logits ==
// top-k of softmax(probs)) + routing list append. One block per token.
// ---------------------------------------------------------------------------
__global__ __launch_bounds__(256) void ln_gate_kernel(
    const float* __restrict__ seq,
    const float* __restrict__ gamma,
    const float* __restrict__ beta,
    const float* __restrict__ Wg,
    const float* __restrict__ bg)
{
    const int t   = blockIdx.x;
    const int tid = threadIdx.x;          // 256 threads, 4 elems each
    const int lane = tid & 31, w = tid >> 5;

    __shared__ float xs[D_DIM];
    __shared__ float red[8];
    __shared__ float logits[E_NUM];
    __shared__ float s_mu, s_rstd;

    const float4 v = reinterpret_cast<const float4*>(seq + (size_t)t * D_DIM)[tid];

    // mean
    float s = v.x + v.y + v.z + v.w;
    #pragma unroll
    for (int o = 16; o; o >>= 1) s += __shfl_xor_sync(0xffffffffu, s, o);
    if (lane == 0) red[w] = s;
    __syncthreads();
    if (tid == 0) {
        float tot = 0.f;
        #pragma unroll
        for (int i = 0; i < 8; i++) tot += red[i];
        s_mu = tot * (1.0f / D_DIM);
    }
    __syncthreads();
    const float mu = s_mu;

    // variance
    float dx = v.x - mu, dy = v.y - mu, dz = v.z - mu, dw = v.w - mu;
    float q = dx*dx + dy*dy + dz*dz + dw*dw;
    #pragma unroll
    for (int o = 16; o; o >>= 1) q += __shfl_xor_sync(0xffffffffu, q, o);
    if (lane == 0) red[w] = q;
    __syncthreads();
    if (tid == 0) {
        float tot = 0.f;
        #pragma unroll
        for (int i = 0; i < 8; i++) tot += red[i];
        s_rstd = rsqrtf(tot * (1.0f / D_DIM) + 1e-5f);
    }
    __syncthreads();
    const float rstd = s_rstd;

    // normalize, scale, write
    const float4 g = reinterpret_cast<const float4*>(gamma)[tid];
    const float4 b = reinterpret_cast<const float4*>(beta)[tid];
    float4 xn;
    xn.x = dx * rstd * g.x + b.x;
    xn.y = dy * rstd * g.y + b.y;
    xn.z = dz * rstd * g.z + b.z;
    xn.w = dw * rstd * g.w + b.w;
    reinterpret_cast<float4*>(xs)[tid] = xn;
    reinterpret_cast<float4*>(g_x + (size_t)t * D_DIM)[tid] = xn;
    __syncthreads();

    // gating logits: warp w computes dot(x, Wg[w])
    const float* wg = Wg + w * D_DIM;
    float acc = 0.f;
    #pragma unroll 8
    for (int d = lane; d < D_DIM; d += 32) acc += xs[d] * wg[d];
    #pragma unroll
    for (int o = 16; o; o >>= 1) acc += __shfl_xor_sync(0xffffffffu, acc, o);
    if (lane == 0) logits[w] = acc + bg[w];
    __syncthreads();

    // top-2 (strict > keeps lowest index on ties, matching lax.top_k)
    if (tid == 0) {
        int b1 = 0; float v1 = logits[0];
        #pragma unroll
        for (int e = 1; e < E_NUM; e++)
            if (logits[e] > v1) { v1 = logits[e]; b1 = e; }
        int b2 = -1; float v2 = -INFINITY;
        #pragma unroll
        for (int e = 0; e < E_NUM; e++)
            if (e != b1 && logits[e] > v2) { v2 = logits[e]; b2 = e; }
        int p1 = atomicAdd(&g_cnt[b1], 1); g_idx[b1][p1] = t;
        int p2 = atomicAdd(&g_cnt[b2], 1); g_idx[b2][p2] = t;
    }
}

// ---------------------------------------------------------------------------
// Kernel 2: gathered expert GEMM.  out[t,:] += 0.5*(x[t] @ We[e]^T + be[e])
// for each token t routed to expert e. 128x128 tile, BK=8, 8x8 per thread.
// grid: (x = n-tile [32], y = m-tile [128], z = expert [8])
// ---------------------------------------------------------------------------
__global__ __launch_bounds__(256) void expert_gemm_kernel(
    const float* __restrict__ We,
    const float* __restrict__ be)
{
    const int e  = blockIdx.z;
    const int mt = blockIdx.y;
    const int nt = blockIdx.x;
    const int cnt = g_cnt[e];
    const int m0 = mt * 128;
    if (m0 >= cnt) return;
    const int n0 = nt * 128;

    __shared__ int   rows[128];
    __shared__ float As[8][128];
    __shared__ float Bs[8][128];

    const int tid = threadIdx.x;
    if (tid < 128) {
        int m = m0 + tid;
        rows[tid] = (m < cnt) ? g_idx[e][m] : -1;
    }
    __syncthreads();

    const int lm  = tid >> 1;          // tile row (A: token slot / B: h slot)
    const int lk4 = (tid & 1) * 4;     // k sub-offset
    const int tx = tid & 15, ty = tid >> 4;

    const int arow = rows[lm];
    const float* aPtr = g_x + (size_t)(arow >= 0 ? arow : 0) * D_DIM;
    const float* bPtr = We + ((size_t)e * H_DIM + n0 + lm) * D_DIM;

    float acc[8][8];
    #pragma unroll
    for (int i = 0; i < 8; i++)
        #pragma unroll
        for (int j = 0; j < 8; j++) acc[i][j] = 0.f;

    for (int k0 = 0; k0 < D_DIM; k0 += 8) {
        float4 av = (arow >= 0)
            ? *reinterpret_cast<const float4*>(aPtr + k0 + lk4)
            : make_float4(0.f, 0.f, 0.f, 0.f);
        float4 bv = *reinterpret_cast<const float4*>(bPtr + k0 + lk4);
        __syncthreads();
        As[lk4+0][lm] = av.x; As[lk4+1][lm] = av.y;
        As[lk4+2][lm] = av.z; As[lk4+3][lm] = av.w;
        Bs[lk4+0][lm] = bv.x; Bs[lk4+1][lm] = bv.y;
        Bs[lk4+2][lm] = bv.z; Bs[lk4+3][lm] = bv.w;
        __syncthreads();
        #pragma unroll
        for (int k = 0; k < 8; k++) {
            float a[8], b[8];
            *reinterpret_cast<float4*>(a)     = *reinterpret_cast<const float4*>(&As[k][ty*8]);
            *reinterpret_cast<float4*>(a + 4) = *reinterpret_cast<const float4*>(&As[k][ty*8+4]);
            *reinterpret_cast<float4*>(b)     = *reinterpret_cast<const float4*>(&Bs[k][tx*8]);
            *reinterpret_cast<float4*>(b + 4) = *reinterpret_cast<const float4*>(&Bs[k][tx*8+4]);
            #pragma unroll
            for (int i = 0; i < 8; i++)
                #pragma unroll
                for (int j = 0; j < 8; j++)
                    acc[i][j] += a[i] * b[j];
        }
    }

    // epilogue: 0.5*(acc + be), atomic accumulate into g_out
    const float* beP = be + (size_t)e * H_DIM + n0 + tx * 8;
    #pragma unroll
    for (int i = 0; i < 8; i++) {
        int r = rows[ty * 8 + i];
        if (r < 0) continue;
        float* outP = g_out + (size_t)r * H_DIM + n0 + tx * 8;
        #pragma unroll
        for (int j = 0; j < 8; j++)
            atomicAdd(outP + j, 0.5f * (acc[i][j] + beP[j]));
    }
}

// ---------------------------------------------------------------------------
// Kernel 3: condense GEMM + bias + residual.
// y[t,d] = sum_h relu(g_out[t,h]) * Wc[d,h] + bc[d] + seq[t,d]
// grid: (x = n-tile over D [8], y = m-tile over T [128])
// ---------------------------------------------------------------------------
__global__ __launch_bounds__(256) void condense_kernel(
    const float* __restrict__ Wc,
    const float* __restrict__ bc,
    const float* __restrict__ seq,
    float* __restrict__ out)
{
    const int mt = blockIdx.y;
    const int nt = blockIdx.x;
    const int m0 = mt * 128;
    const int n0 = nt * 128;

    __shared__ float As[8][128];
    __shared__ float Bs[8][128];

    const int tid = threadIdx.x;
    const int lm  = tid >> 1;
    const int lk4 = (tid & 1) * 4;
    const int tx = tid & 15, ty = tid >> 4;

    const float* aPtr = g_out + (size_t)(m0 + lm) * H_DIM;
    const float* bPtr = Wc    + (size_t)(n0 + lm) * H_DIM;

    float acc[8][8];
    #pragma unroll
    for (int i = 0; i < 8; i++)
        #pragma unroll
        for (int j = 0; j < 8; j++) acc[i][j] = 0.f;

    for (int k0 = 0; k0 < H_DIM; k0 += 8) {
        float4 av = *reinterpret_cast<const float4*>(aPtr + k0 + lk4);
        float4 bv = *reinterpret_cast<const float4*>(bPtr + k0 + lk4);
        av.x = fmaxf(av.x, 0.f); av.y = fmaxf(av.y, 0.f);
        av.z = fmaxf(av.z, 0.f); av.w = fmaxf(av.w, 0.f);
        __syncthreads();
        As[lk4+0][lm] = av.x; As[lk4+1][lm] = av.y;
        As[lk4+2][lm] = av.z; As[lk4+3][lm] = av.w;
        Bs[lk4+0][lm] = bv.x; Bs[lk4+1][lm] = bv.y;
        Bs[lk4+2][lm] = bv.z; Bs[lk4+3][lm] = bv.w;
        __syncthreads();
        #pragma unroll
        for (int k = 0; k < 8; k++) {
            float a[8], b[8];
            *reinterpret_cast<float4*>(a)     = *reinterpret_cast<const float4*>(&As[k][ty*8]);
            *reinterpret_cast<float4*>(a + 4) = *reinterpret_cast<const float4*>(&As[k][ty*8+4]);
            *reinterpret_cast<float4*>(b)     = *reinterpret_cast<const float4*>(&Bs[k][tx*8]);
            *reinterpret_cast<float4*>(b + 4) = *reinterpret_cast<const float4*>(&Bs[k][tx*8+4]);
            #pragma unroll
            for (int i = 0; i < 8; i++)
                #pragma unroll
                for (int j = 0; j < 8; j++)
                    acc[i][j] += a[i] * b[j];
        }
    }

    // epilogue: + bc + residual, vectorized stores
    #pragma unroll
    for (int i = 0; i < 8; i++) {
        const int t = m0 + ty * 8 + i;
        const size_t base = (size_t)t * D_DIM + n0 + tx * 8;
        #pragma unroll
        for (int h = 0; h < 2; h++) {
            float4 r = *reinterpret_cast<const float4*>(seq + base + h * 4);
            float4 c = *reinterpret_cast<const float4*>(bc + n0 + tx * 8 + h * 4);
            float4 o;
            o.x = acc[i][h*4+0] + c.x + r.x;
            o.y = acc[i][h*4+1] + c.y + r.y;
            o.z = acc[i][h*4+2] + c.z + r.z;
            o.w = acc[i][h*4+3] + c.w + r.w;
            *reinterpret_cast<float4*>(out + base + h * 4) = o;
        }
    }
}

// ---------------------------------------------------------------------------
extern "C" void kernel_launch(void* const* d_in, const int* in_sizes, int n_in,
                              void* d_out, int out_size)
{
    const float* seq   = (const float*)d_in[0];  // [4,4096,1024]
    const float* gamma = (const float*)d_in[1];  // [1024]
    const float* beta  = (const float*)d_in[2];  // [1024]
    const float* Wg    = (const float*)d_in[3];  // [8,1024]
    const float* bg    = (const float*)d_in[4];  // [8]
    const float* We    = (const float*)d_in[5];  // [8,4096,1024]
    const float* be    = (const float*)d_in[6];  // [8,4096]
    const float* Wc    = (const float*)d_in[7];  // [1024,4096]
    const float* bc    = (const float*)d_in[8];  // [1024]
    // d_in[9] = top_k (fixed at 2)
    float* out = (float*)d_out;

    init_kernel<<<4096, 256>>>();
    ln_gate_kernel<<<T_TOK, 256>>>(seq, gamma, beta, Wg, bg);
    {
        dim3 grid(H_DIM / 128, T_TOK / 128, E_NUM);
        expert_gemm_kernel<<<grid, 256>>>(We, be);
    }
    {
        dim3 grid(D_DIM / 128, T_TOK / 128);
        condense_kernel<<<grid, 256>>>(Wc, bc, seq, out);
    }
}

// round 3
// speedup vs baseline: 1.6809x; 1.6809x over previous
#include <cuda_runtime.h>
#include <cstdint>
#include <math.h>
#include <mma.h>

using namespace nvcuda;

// Problem dims (fixed)
#define T_TOK 16384
#define D_DIM 1024
#define H_DIM 4096
#define E_NUM 8

// ---------------------------------------------------------------------------
// Scratch (device globals: allocation-free rule)
// ---------------------------------------------------------------------------
__device__ float g_x[(size_t)T_TOK * D_DIM];          // LN output        64 MB
__device__ float g_part[(size_t)T_TOK * 2 * H_DIM];   // per-slot expert 512 MB
__device__ float g_act[(size_t)T_TOK * H_DIM];        // relu(avg)       256 MB
__device__ int   g_idx[E_NUM][T_TOK];                 // packed (t<<1)|slot
__device__ int   g_cnt[E_NUM];

// ---------------------------------------------------------------------------
// cp.async helpers (sm_80+, no arch suffix needed)
// ---------------------------------------------------------------------------
__device__ __forceinline__ uint32_t smem_u32(const void* p) {
    uint32_t a;
    asm("{ .reg .u64 t; cvta.to.shared.u64 t, %1; cvt.u32.u64 %0, t; }"
        : "=r"(a) : "l"(p));
    return a;
}
#define CP_ASYNC16(dst, src) \
    asm volatile("cp.async.cg.shared.global [%0], [%1], 16;" :: "r"(dst), "l"(src))
#define CP_ASYNC16Z(dst, src, sz) \
    asm volatile("cp.async.cg.shared.global [%0], [%1], 16, %2;" :: "r"(dst), "l"(src), "r"(sz))
#define CP_COMMIT() asm volatile("cp.async.commit_group;" ::: "memory")
#define CP_WAIT(n)  asm volatile("cp.async.wait_group %0;" :: "n"(n) : "memory")

// ---------------------------------------------------------------------------
// SMEM layout (dynamic). A/B tiles: 128 rows x 16 floats, padded ld=20.
// ---------------------------------------------------------------------------
#define LDAB      20                 // padded leading dim (floats)
#define AB_STAGE  (128 * LDAB * 4)   // 10240 bytes
#define SM_ROWS   0
#define SM_A0     1024
#define SM_B0     (SM_A0 + 2 * AB_STAGE)           // 21504
#define SM_CS     (SM_B0 + 2 * AB_STAGE)           // 41984
#define LDC       132
#define SMEM_BYTES (SM_CS + 128 * LDC * 4)         // 109568

// ---------------------------------------------------------------------------
// Kernel A: zero routing counters
// ---------------------------------------------------------------------------
__global__ void zero_cnt_kernel() { if (threadIdx.x < E_NUM) g_cnt[threadIdx.x] = 0; }

// ---------------------------------------------------------------------------
// Kernel B: fused LayerNorm + gate top-2 (softmax monotone -> skip) + routing
// ---------------------------------------------------------------------------
__global__ __launch_bounds__(256) void ln_gate_kernel(
    const float* __restrict__ seq, const float* __restrict__ gamma,
    const float* __restrict__ beta, const float* __restrict__ Wg,
    const float* __restrict__ bg)
{
    const int t = blockIdx.x, tid = threadIdx.x;
    const int lane = tid & 31, w = tid >> 5;
    __shared__ float xs[D_DIM], red[8], logits[E_NUM], s_mu, s_rstd;

    const float4 v = reinterpret_cast<const float4*>(seq + (size_t)t * D_DIM)[tid];
    float s = v.x + v.y + v.z + v.w;
    #pragma unroll
    for (int o = 16; o; o >>= 1) s += __shfl_xor_sync(~0u, s, o);
    if (lane == 0) red[w] = s;
    __syncthreads();
    if (tid == 0) {
        float tot = 0.f;
        #pragma unroll
        for (int i = 0; i < 8; i++) tot += red[i];
        s_mu = tot * (1.0f / D_DIM);
    }
    __syncthreads();
    const float mu = s_mu;
    float dx = v.x - mu, dy = v.y - mu, dz = v.z - mu, dw = v.w - mu;
    float q = dx * dx + dy * dy + dz * dz + dw * dw;
    #pragma unroll
    for (int o = 16; o; o >>= 1) q += __shfl_xor_sync(~0u, q, o);
    if (lane == 0) red[w] = q;
    __syncthreads();
    if (tid == 0) {
        float tot = 0.f;
        #pragma unroll
        for (int i = 0; i < 8; i++) tot += red[i];
        s_rstd = rsqrtf(tot * (1.0f / D_DIM) + 1e-5f);
    }
    __syncthreads();
    const float rstd = s_rstd;

    const float4 g = reinterpret_cast<const float4*>(gamma)[tid];
    const float4 b = reinterpret_cast<const float4*>(beta)[tid];
    float4 xn;
    xn.x = dx * rstd * g.x + b.x; xn.y = dy * rstd * g.y + b.y;
    xn.z = dz * rstd * g.z + b.z; xn.w = dw * rstd * g.w + b.w;
    reinterpret_cast<float4*>(xs)[tid] = xn;
    reinterpret_cast<float4*>(g_x + (size_t)t * D_DIM)[tid] = xn;
    __syncthreads();

    const float* wg = Wg + w * D_DIM;
    float acc = 0.f;
    #pragma unroll 8
    for (int d = lane; d < D_DIM; d += 32) acc += xs[d] * wg[d];
    #pragma unroll
    for (int o = 16; o; o >>= 1) acc += __shfl_xor_sync(~0u, acc, o);
    if (lane == 0) logits[w] = acc + bg[w];
    __syncthreads();

    if (tid == 0) {
        int b1 = 0; float v1 = logits[0];
        #pragma unroll
        for (int e = 1; e < E_NUM; e++) if (logits[e] > v1) { v1 = logits[e]; b1 = e; }
        int b2 = -1; float v2 = -INFINITY;
        #pragma unroll
        for (int e = 0; e < E_NUM; e++) if (e != b1 && logits[e] > v2) { v2 = logits[e]; b2 = e; }
        int p1 = atomicAdd(&g_cnt[b1], 1); g_idx[b1][p1] = (t << 1) | 0;
        int p2 = atomicAdd(&g_cnt[b2], 1); g_idx[b2][p2] = (t << 1) | 1;
    }
}

// ---------------------------------------------------------------------------
// Shared GEMM core: 128x128 tile, BK=16, wmma tf32 m16n16k8.
// 8 warps: 2 (m) x 4 (n); warp tile 64x32 = 4x2 fragments.
// A rows gathered via srcA pointers (NULL -> zero-fill).
// After the loop, the C tile sits in smem Cs[128][LDC].
// ---------------------------------------------------------------------------
struct GemmPtrs {
    const float* a0; const float* a1;   // per-thread A row pointers (chunk0/1)
    const float* b0; const float* b1;   // per-thread B row pointers
    uint32_t da0, da1, db0, db1;        // smem dst offsets within stage
};

__device__ __forceinline__ void gemm_core(
    char* smem, uint32_t sb, const GemmPtrs& P, int K_total)
{
    const int tid = threadIdx.x, wid = tid >> 5;
    const int wm = (wid >> 2) * 64, wn = (wid & 3) * 32;

    wmma::fragment<wmma::accumulator, 16, 16, 8, float> acc[4][2];
    #pragma unroll
    for (int i = 0; i < 4; i++)
        #pragma unroll
        for (int j = 0; j < 2; j++) wmma::fill_fragment(acc[i][j], 0.0f);

    const int NC = K_total / 16;
    // prefetch stage 0
    {
        uint32_t ab = sb + SM_A0, bb = sb + SM_B0;
        CP_ASYNC16Z(ab + P.da0, P.a0, P.a0 ? 16u : 0u);
        CP_ASYNC16Z(ab + P.da1, P.a1, P.a1 ? 16u : 0u);
        CP_ASYNC16(bb + P.db0, P.b0);
        CP_ASYNC16(bb + P.db1, P.b1);
        CP_COMMIT();
    }
    for (int c = 0; c < NC; ++c) {
        const int q = c + 1;
        if (q < NC) {
            uint32_t st = (uint32_t)(q & 1) * AB_STAGE;
            uint32_t ab = sb + SM_A0 + st, bb = sb + SM_B0 + st;
            CP_ASYNC16Z(ab + P.da0, P.a0 + q * 16, P.a0 ? 16u : 0u);
            CP_ASYNC16Z(ab + P.da1, P.a1 + q * 16, P.a1 ? 16u : 0u);
            CP_ASYNC16(bb + P.db0, P.b0 + q * 16);
            CP_ASYNC16(bb + P.db1, P.b1 + q * 16);
            CP_COMMIT();
            CP_WAIT(1);
        } else {
            CP_WAIT(0);
        }
        __syncthreads();
        const float* As = (const float*)(smem + SM_A0 + (c & 1) * AB_STAGE);
        const float* Bs = (const float*)(smem + SM_B0 + (c & 1) * AB_STAGE);
        #pragma unroll
        for (int kk = 0; kk < 16; kk += 8) {
            wmma::fragment<wmma::matrix_a, 16, 16, 8, wmma::precision::tf32, wmma::row_major> af[4];
            wmma::fragment<wmma::matrix_b, 16, 16, 8, wmma::precision::tf32, wmma::col_major> bf[2];
            #pragma unroll
            for (int i = 0; i < 4; i++)
                wmma::load_matrix_sync(af[i], As + (wm + i * 16) * LDAB + kk, LDAB);
            #pragma unroll
            for (int j = 0; j < 2; j++)
                wmma::load_matrix_sync(bf[j], Bs + (wn + j * 16) * LDAB + kk, LDAB);
            #pragma unroll
            for (int i = 0; i < 4; i++)
                #pragma unroll
                for (int j = 0; j < 2; j++)
                    wmma::mma_sync(acc[i][j], af[i], bf[j], acc[i][j]);
        }
        __syncthreads();
    }
    // stage C into smem
    float* Cs = (float*)(smem + SM_CS);
    #pragma unroll
    for (int i = 0; i < 4; i++)
        #pragma unroll
        for (int j = 0; j < 2; j++)
            wmma::store_matrix_sync(Cs + (wm + i * 16) * LDC + wn + j * 16,
                                    acc[i][j], LDC, wmma::mem_row_major);
    __syncthreads();
}

// ---------------------------------------------------------------------------
// Kernel C: expert GEMM.  Tile: M=128 gathered tokens, N=128 hidden, K=1024.
// grid: (x = H/128 = 32, y = T/128 = 128, z = 8)
// ---------------------------------------------------------------------------
__global__ __launch_bounds__(256, 2) void expert_tc(
    const float* __restrict__ We, const float* __restrict__ be)
{
    const int e = blockIdx.z, mt = blockIdx.y, nt = blockIdx.x;
    const int cnt = g_cnt[e];
    const int m0 = mt * 128;
    if (m0 >= cnt) return;
    const int n0 = nt * 128;

    extern __shared__ char smem[];
    const uint32_t sb = smem_u32(smem);
    const int tid = threadIdx.x;

    int* rows = (int*)(smem + SM_ROWS);
    if (tid < 128) {
        int m = m0 + tid;
        rows[tid] = (m < cnt) ? g_idx[e][m] : -1;
    }
    __syncthreads();

    // per-thread transfer chunks: chunk = row*4 + seg (16B each)
    const int r0 = tid >> 2, seg = tid & 3;   // rows 0..63 / +64
    GemmPtrs P;
    {
        int pk0 = rows[r0], pk1 = rows[r0 + 64];
        P.a0 = (pk0 >= 0) ? g_x + (size_t)(pk0 >> 1) * D_DIM + seg * 4 : nullptr;
        P.a1 = (pk1 >= 0) ? g_x + (size_t)(pk1 >> 1) * D_DIM + seg * 4 : nullptr;
        const float* bBase = We + ((size_t)e * H_DIM + n0) * D_DIM;
        P.b0 = bBase + (size_t)r0 * D_DIM + seg * 4;
        P.b1 = bBase + (size_t)(r0 + 64) * D_DIM + seg * 4;
        P.da0 = r0 * (LDAB * 4) + seg * 16;
        P.da1 = (r0 + 64) * (LDAB * 4) + seg * 16;
        P.db0 = P.da0; P.db1 = P.da1;
    }

    gemm_core(smem, sb, P, D_DIM);

    // scatter epilogue: thread -> row tid>>1, col half (tid&1)*64
    const float* Cs = (const float*)(smem + SM_CS);
    const int r = tid >> 1, ch = (tid & 1) * 64;
    const int pk = rows[r];
    if (pk >= 0) {
        float* op = g_part + (size_t)pk * H_DIM + n0 + ch;
        const float* bp = be + (size_t)e * H_DIM + n0 + ch;
        const float* cp = Cs + r * LDC + ch;
        #pragma unroll
        for (int j = 0; j < 64; j += 4) {
            float4 bv = *reinterpret_cast<const float4*>(bp + j);
            float4 o;
            o.x = cp[j + 0] + bv.x; o.y = cp[j + 1] + bv.y;
            o.z = cp[j + 2] + bv.z; o.w = cp[j + 3] + bv.w;
            *reinterpret_cast<float4*>(op + j) = o;
        }
    }
}

// ---------------------------------------------------------------------------
// Kernel D: act[t][h] = relu(0.5*(part[2t][h] + part[2t+1][h]))
// ---------------------------------------------------------------------------
__global__ void relu_combine_kernel() {
    const size_t n4 = (size_t)T_TOK * H_DIM / 4;
    const size_t stride = (size_t)gridDim.x * blockDim.x;
    for (size_t i = (size_t)blockIdx.x * blockDim.x + threadIdx.x; i < n4; i += stride) {
        size_t el = i * 4;
        size_t t = el / H_DIM, h = el % H_DIM;
        const float4 a = *reinterpret_cast<const float4*>(g_part + (t * 2) * (size_t)H_DIM + h);
        const float4 b = *reinterpret_cast<const float4*>(g_part + (t * 2 + 1) * (size_t)H_DIM + h);
        float4 o;
        o.x = fmaxf(0.5f * (a.x + b.x), 0.f);
        o.y = fmaxf(0.5f * (a.y + b.y), 0.f);
        o.z = fmaxf(0.5f * (a.z + b.z), 0.f);
        o.w = fmaxf(0.5f * (a.w + b.w), 0.f);
        *reinterpret_cast<float4*>(g_act + t * (size_t)H_DIM + h) = o;
    }
}

// ---------------------------------------------------------------------------
// Kernel E: condense GEMM + bias + residual.  M=128, N=128, K=4096.
// grid: (x = D/128 = 8, y = T/128 = 128)
// ---------------------------------------------------------------------------
__global__ __launch_bounds__(256, 2) void condense_tc(
    const float* __restrict__ Wc, const float* __restrict__ bc,
    const float* __restrict__ seq, float* __restrict__ out)
{
    const int mt = blockIdx.y, nt = blockIdx.x;
    const int m0 = mt * 128, n0 = nt * 128;

    extern __shared__ char smem[];
    const uint32_t sb = smem_u32(smem);
    const int tid = threadIdx.x;

    const int r0 = tid >> 2, seg = tid & 3;
    GemmPtrs P;
    {
        P.a0 = g_act + (size_t)(m0 + r0) * H_DIM + seg * 4;
        P.a1 = g_act + (size_t)(m0 + r0 + 64) * H_DIM + seg * 4;
        const float* bBase = Wc + (size_t)n0 * H_DIM;
        P.b0 = bBase + (size_t)r0 * H_DIM + seg * 4;
        P.b1 = bBase + (size_t)(r0 + 64) * H_DIM + seg * 4;
        P.da0 = r0 * (LDAB * 4) + seg * 16;
        P.da1 = (r0 + 64) * (LDAB * 4) + seg * 16;
        P.db0 = P.da0; P.db1 = P.da1;
    }

    gemm_core(smem, sb, P, H_DIM);

    const float* Cs = (const float*)(smem + SM_CS);
    const int r = tid >> 1, ch = (tid & 1) * 64;
    const int t = m0 + r;
    const size_t base = (size_t)t * D_DIM + n0 + ch;
    const float* cp = Cs + r * LDC + ch;
    #pragma unroll
    for (int j = 0; j < 64; j += 4) {
        float4 cv = *reinterpret_cast<const float4*>(bc + n0 + ch + j);
        float4 rv = *reinterpret_cast<const float4*>(seq + base + j);
        float4 o;
        o.x = cp[j + 0] + cv.x + rv.x;
        o.y = cp[j + 1] + cv.y + rv.y;
        o.z = cp[j + 2] + cv.z + rv.z;
        o.w = cp[j + 3] + cv.w + rv.w;
        *reinterpret_cast<float4*>(out + base + j) = o;
    }
}

// ---------------------------------------------------------------------------
extern "C" void kernel_launch(void* const* d_in, const int* in_sizes, int n_in,
                              void* d_out, int out_size)
{
    const float* seq   = (const float*)d_in[0];
    const float* gamma = (const float*)d_in[1];
    const float* beta  = (const float*)d_in[2];
    const float* Wg    = (const float*)d_in[3];
    const float* bg    = (const float*)d_in[4];
    const float* We    = (const float*)d_in[5];
    const float* be    = (const float*)d_in[6];
    const float* Wc    = (const float*)d_in[7];
    const float* bc    = (const float*)d_in[8];
    float* out = (float*)d_out;

    cudaFuncSetAttribute(expert_tc, cudaFuncAttributeMaxDynamicSharedMemorySize, SMEM_BYTES);
    cudaFuncSetAttribute(condense_tc, cudaFuncAttributeMaxDynamicSharedMemorySize, SMEM_BYTES);

    zero_cnt_kernel<<<1, 32>>>();
    ln_gate_kernel<<<T_TOK, 256>>>(seq, gamma, beta, Wg, bg);
    {
        dim3 grid(H_DIM / 128, T_TOK / 128, E_NUM);
        expert_tc<<<grid, 256, SMEM_BYTES>>>(We, be);
    }
    relu_combine_kernel<<<4096, 256>>>();
    {
        dim3 grid(D_DIM / 128, T_TOK / 128);
        condense_tc<<<grid, 256, SMEM_BYTES>>>(Wc, bc, seq, out);
    }
}

// round 7
// speedup vs baseline: 3.0128x; 1.7924x over previous
#include <cuda_runtime.h>
#include <cstdint>
#include <math.h>

// Problem dims (fixed)
#define T_TOK 16384
#define D_DIM 1024
#define H_DIM 4096
#define E_NUM 8

// ---------------------------------------------------------------------------
// Scratch (device globals: allocation-free rule)
// ---------------------------------------------------------------------------
__device__ float g_x[(size_t)T_TOK * D_DIM];          // LN out (tf32-rounded)
__device__ float g_part[(size_t)T_TOK * 2 * H_DIM];   // per-slot expert out
__device__ float g_act[(size_t)T_TOK * H_DIM];        // relu(avg) (tf32-rounded)
__device__ float g_We[(size_t)E_NUM * H_DIM * D_DIM]; // tf32-rounded We
__device__ float g_Wc[(size_t)D_DIM * H_DIM];         // tf32-rounded Wc
__device__ int   g_idx[E_NUM][T_TOK];                 // packed (t<<1)|slot
__device__ int   g_cnt[E_NUM];

// ---------------------------------------------------------------------------
// PTX helpers
// ---------------------------------------------------------------------------
__device__ __forceinline__ uint32_t smem_u32(const void* p) {
    uint32_t a;
    asm("{ .reg .u64 t; cvta.to.shared.u64 t, %1; cvt.u32.u64 %0, t; }"
        : "=r"(a) : "l"(p));
    return a;
}
#define CP_ASYNC16(dst, src) \
    asm volatile("cp.async.cg.shared.global [%0], [%1], 16;" :: "r"(dst), "l"(src))
#define CP_ASYNC16Z(dst, src, sz) \
    asm volatile("cp.async.cg.shared.global [%0], [%1], 16, %2;" :: "r"(dst), "l"(src), "r"(sz))
#define CP_COMMIT() asm volatile("cp.async.commit_group;" ::: "memory")
#define CP_WAIT(n)  asm volatile("cp.async.wait_group %0;" :: "n"(n) : "memory")

__device__ __forceinline__ uint32_t f2tf32(float f) {
    uint32_t o;
    asm("cvt.rna.tf32.f32 %0, %1;" : "=r"(o) : "f"(f));
    return o;
}

__device__ __forceinline__ void mma8(float* c, uint32_t a0, uint32_t a1,
                                     uint32_t a2, uint32_t a3,
                                     uint32_t b0, uint32_t b1) {
    asm volatile(
        "mma.sync.aligned.m16n8k8.row.col.f32.tf32.tf32.f32 "
        "{%0,%1,%2,%3}, {%4,%5,%6,%7}, {%8,%9}, {%0,%1,%2,%3};"
        : "+f"(c[0]), "+f"(c[1]), "+f"(c[2]), "+f"(c[3])
        : "r"(a0), "r"(a1), "r"(a2), "r"(a3), "r"(b0), "r"(b1));
}

// ---------------------------------------------------------------------------
// SMEM layout: rows[128] @0, A stages @1024 (3 x 16KB), B stages after.
// C staging (128 x 132 fp32 = 67.5KB) reuses the A/B region post-mainloop.
// ---------------------------------------------------------------------------
#define SM_ROWS 0
#define SM_A0   1024
#define ST_SZ   16384
#define SM_B0   (SM_A0 + 3 * ST_SZ)       // 50176
#define SMEM_BYTES (SM_B0 + 3 * ST_SZ)    // 99328
#define SM_CS   SM_A0
#define LDC     132

// ---------------------------------------------------------------------------
// Small kernels
// ---------------------------------------------------------------------------
__global__ void zero_cnt_kernel() { if (threadIdx.x < E_NUM) g_cnt[threadIdx.x] = 0; }

__global__ void cvt_kernel(const float* __restrict__ src, float* __restrict__ dst, int n4) {
    int i = blockIdx.x * blockDim.x + threadIdx.x;
    const int stride = gridDim.x * blockDim.x;
    for (; i < n4; i += stride) {
        float4 v = reinterpret_cast<const float4*>(src)[i];
        uint4 o;
        o.x = f2tf32(v.x); o.y = f2tf32(v.y); o.z = f2tf32(v.z); o.w = f2tf32(v.w);
        reinterpret_cast<uint4*>(dst)[i] = o;
    }
}

// ---------------------------------------------------------------------------
// Fused LayerNorm + gate top-2 (softmax monotone -> skip) + routing
// ---------------------------------------------------------------------------
__global__ __launch_bounds__(256) void ln_gate_kernel(
    const float* __restrict__ seq, const float* __restrict__ gamma,
    const float* __restrict__ beta, const float* __restrict__ Wg,
    const float* __restrict__ bg)
{
    const int t = blockIdx.x, tid = threadIdx.x;
    const int lane = tid & 31, w = tid >> 5;
    __shared__ float xs[D_DIM], red[8], logits[E_NUM], s_mu, s_rstd;

    const float4 v = reinterpret_cast<const float4*>(seq + (size_t)t * D_DIM)[tid];
    float s = v.x + v.y + v.z + v.w;
    #pragma unroll
    for (int o = 16; o; o >>= 1) s += __shfl_xor_sync(~0u, s, o);
    if (lane == 0) red[w] = s;
    __syncthreads();
    if (tid == 0) {
        float tot = 0.f;
        #pragma unroll
        for (int i = 0; i < 8; i++) tot += red[i];
        s_mu = tot * (1.0f / D_DIM);
    }
    __syncthreads();
    const float mu = s_mu;
    float dx = v.x - mu, dy = v.y - mu, dz = v.z - mu, dw = v.w - mu;
    float q = dx * dx + dy * dy + dz * dz + dw * dw;
    #pragma unroll
    for (int o = 16; o; o >>= 1) q += __shfl_xor_sync(~0u, q, o);
    if (lane == 0) red[w] = q;
    __syncthreads();
    if (tid == 0) {
        float tot = 0.f;
        #pragma unroll
        for (int i = 0; i < 8; i++) tot += red[i];
        s_rstd = rsqrtf(tot * (1.0f / D_DIM) + 1e-5f);
    }
    __syncthreads();
    const float rstd = s_rstd;

    const float4 g = reinterpret_cast<const float4*>(gamma)[tid];
    const float4 b = reinterpret_cast<const float4*>(beta)[tid];
    float4 xn;
    xn.x = dx * rstd * g.x + b.x; xn.y = dy * rstd * g.y + b.y;
    xn.z = dz * rstd * g.z + b.z; xn.w = dw * rstd * g.w + b.w;
    reinterpret_cast<float4*>(xs)[tid] = xn;
    uint4 xr;   // tf32-round for GEMM A operand
    xr.x = f2tf32(xn.x); xr.y = f2tf32(xn.y); xr.z = f2tf32(xn.z); xr.w = f2tf32(xn.w);
    reinterpret_cast<uint4*>(g_x + (size_t)t * D_DIM)[tid] = xr;
    __syncthreads();

    const float* wg = Wg + w * D_DIM;
    float acc = 0.f;
    #pragma unroll 8
    for (int d = lane; d < D_DIM; d += 32) acc += xs[d] * wg[d];
    #pragma unroll
    for (int o = 16; o; o >>= 1) acc += __shfl_xor_sync(~0u, acc, o);
    if (lane == 0) logits[w] = acc + bg[w];
    __syncthreads();

    if (tid == 0) {
        int b1 = 0; float v1 = logits[0];
        #pragma unroll
        for (int e = 1; e < E_NUM; e++) if (logits[e] > v1) { v1 = logits[e]; b1 = e; }
        int b2 = -1; float v2 = -INFINITY;
        #pragma unroll
        for (int e = 0; e < E_NUM; e++) if (e != b1 && logits[e] > v2) { v2 = logits[e]; b2 = e; }
        int p1 = atomicAdd(&g_cnt[b1], 1); g_idx[b1][p1] = (t << 1) | 0;
        int p2 = atomicAdd(&g_cnt[b2], 1); g_idx[b2][p2] = (t << 1) | 1;
    }
}

// ---------------------------------------------------------------------------
// GEMM core: 128x128 tile, BK=32, 3-stage cp.async, mma.m16n8k8.tf32.
// 8 warps = 2(m) x 4(n); warp tile 64x32 = 4 m-frags x 4 n-frags.
// smem float4-swizzle: float4 col (c>>2) stored at (c>>2) ^ (row&7).
// Consumer rows are always ≡ g (mod 8), so load addrs are conflict-free.
// Result left staged in smem Cs[128][LDC].
// ---------------------------------------------------------------------------
__device__ __forceinline__ void gemm_core(
    char* smem, uint32_t sb,
    const float* aSrc, uint32_t aSz, const float* bSrc, int NC)
{
    const int tid = threadIdx.x, lane = tid & 31, wid = tid >> 5;
    const int g = lane >> 2, t = lane & 3;
    const int wm = (wid >> 2) * 64, wn = (wid & 3) * 32;

    // cp.async thread mapping: row ra = tid>>1, float4 groups j4b..j4b+3
    const int ra = tid >> 1, j4b = (tid & 1) * 4;
    uint32_t aDst[4], bDst[4];
    #pragma unroll
    for (int j = 0; j < 4; j++) {
        uint32_t sw = (uint32_t)(ra * 8 + ((j4b + j) ^ (ra & 7))) * 16;
        aDst[j] = sb + SM_A0 + sw;
        bDst[j] = sb + SM_B0 + sw;
    }

    float acc[4][4][4];
    #pragma unroll
    for (int mi = 0; mi < 4; mi++)
        #pragma unroll
        for (int nf = 0; nf < 4; nf++)
            #pragma unroll
            for (int k = 0; k < 4; k++) acc[mi][nf][k] = 0.f;

    // prologue: stages 0,1
    #pragma unroll
    for (int s = 0; s < 2; s++) {
        uint32_t off = (uint32_t)s * ST_SZ;
        const float* ap = aSrc + s * 32;
        const float* bp = bSrc + s * 32;
        #pragma unroll
        for (int j = 0; j < 4; j++) {
            CP_ASYNC16Z(aDst[j] + off, ap + (j4b + j) * 4, aSz);
            CP_ASYNC16(bDst[j] + off, bp + (j4b + j) * 4);
        }
        CP_COMMIT();
    }

    for (int kc = 0; kc < NC; kc++) {
        CP_WAIT(1);
        __syncthreads();
        const int qs = kc + 2;
        if (qs < NC) {
            uint32_t off = (uint32_t)(qs % 3) * ST_SZ;
            const float* ap = aSrc + qs * 32;
            const float* bp = bSrc + qs * 32;
            #pragma unroll
            for (int j = 0; j < 4; j++) {
                CP_ASYNC16Z(aDst[j] + off, ap + (j4b + j) * 4, aSz);
                CP_ASYNC16(bDst[j] + off, bp + (j4b + j) * 4);
            }
            CP_COMMIT();
        } else {
            CP_COMMIT();
        }

        const uint32_t* As = (const uint32_t*)(smem + SM_A0 + (kc % 3) * ST_SZ);
        const uint32_t* Bs = (const uint32_t*)(smem + SM_B0 + (kc % 3) * ST_SZ);
        #pragma unroll
        for (int kk = 0; kk < 4; kk++) {
            const int c0 = ((kk * 2) ^ g) * 4 + t;       // k-lo swizzled col
            const int c1 = ((kk * 2 + 1) ^ g) * 4 + t;   // k-hi
            uint32_t bf[4][2];
            #pragma unroll
            for (int nf = 0; nf < 4; nf++) {
                const int bb = (wn + nf * 8 + g) * 32;
                bf[nf][0] = Bs[bb + c0];
                bf[nf][1] = Bs[bb + c1];
            }
            #pragma unroll
            for (int mi = 0; mi < 4; mi++) {
                const int ab = (wm + mi * 16 + g) * 32;
                uint32_t a0 = As[ab + c0];         // (g,   t)
                uint32_t a1 = As[ab + 256 + c0];   // (g+8, t)
                uint32_t a2 = As[ab + c1];         // (g,   t+4)
                uint32_t a3 = As[ab + 256 + c1];   // (g+8, t+4)
                #pragma unroll
                for (int nf = 0; nf < 4; nf++)
                    mma8(acc[mi][nf], a0, a1, a2, a3, bf[nf][0], bf[nf][1]);
            }
        }
    }
    CP_WAIT(0);
    __syncthreads();

    // stage C into smem
    float* Cs = (float*)(smem + SM_CS);
    #pragma unroll
    for (int mi = 0; mi < 4; mi++) {
        const int r0 = wm + mi * 16 + g;
        #pragma unroll
        for (int nf = 0; nf < 4; nf++) {
            const int c = wn + nf * 8 + 2 * t;
            *reinterpret_cast<float2*>(&Cs[r0 * LDC + c]) =
                make_float2(acc[mi][nf][0], acc[mi][nf][1]);
            *reinterpret_cast<float2*>(&Cs[(r0 + 8) * LDC + c]) =
                make_float2(acc[mi][nf][2], acc[mi][nf][3]);
        }
    }
    __syncthreads();
}

// ---------------------------------------------------------------------------
// Expert GEMM: M=128 gathered tokens, N=128 hidden, K=1024.
// grid: (H/128 = 32, T/128 = 128, 8)
// ---------------------------------------------------------------------------
__global__ __launch_bounds__(256, 2) void expert_tc(const float* __restrict__ be)
{
    const int e = blockIdx.z, mt = blockIdx.y, nt = blockIdx.x;
    const int cnt = g_cnt[e];
    const int m0 = mt * 128;
    if (m0 >= cnt) return;
    const int n0 = nt * 128;

    extern __shared__ char smem[];
    const uint32_t sb = smem_u32(smem);
    const int tid = threadIdx.x;

    int* rows = (int*)(smem + SM_ROWS);
    if (tid < 128) {
        int m = m0 + tid;
        rows[tid] = (m < cnt) ? g_idx[e][m] : -1;
    }
    __syncthreads();

    const int ra = tid >> 1;
    const int pk = rows[ra];
    const float* aSrc = g_x + (size_t)(pk >= 0 ? (pk >> 1) : 0) * D_DIM;
    const uint32_t aSz = (pk >= 0) ? 16u : 0u;
    const float* bSrc = g_We + ((size_t)e * H_DIM + n0 + ra) * D_DIM;

    gemm_core(smem, sb, aSrc, aSz, bSrc, D_DIM / 32);

    // scatter epilogue: thread -> row tid>>1, col half (tid&1)*64
    const float* Cs = (const float*)(smem + SM_CS);
    const int r = tid >> 1, ch = (tid & 1) * 64;
    const int pko = rows[r];
    if (pko >= 0) {
        float* op = g_part + (size_t)pko * H_DIM + n0 + ch;
        const float* bp = be + (size_t)e * H_DIM + n0 + ch;
        const float* cp = Cs + r * LDC + ch;
        #pragma unroll
        for (int j = 0; j < 64; j += 4) {
            float4 bv = *reinterpret_cast<const float4*>(bp + j);
            float4 o;
            o.x = cp[j + 0] + bv.x; o.y = cp[j + 1] + bv.y;
            o.z = cp[j + 2] + bv.z; o.w = cp[j + 3] + bv.w;
            *reinterpret_cast<float4*>(op + j) = o;
        }
    }
}

// ---------------------------------------------------------------------------
// act[t][h] = tf32(relu(0.5*(part[2t][h] + part[2t+1][h])))
// ---------------------------------------------------------------------------
__global__ void relu_combine_kernel() {
    const size_t n4 = (size_t)T_TOK * H_DIM / 4;
    const size_t stride = (size_t)gridDim.x * blockDim.x;
    for (size_t i = (size_t)blockIdx.x * blockDim.x + threadIdx.x; i < n4; i += stride) {
        size_t el = i * 4;
        size_t t = el / H_DIM, h = el % H_DIM;
        const float4 a = *reinterpret_cast<const float4*>(g_part + (t * 2) * (size_t)H_DIM + h);
        const float4 b = *reinterpret_cast<const float4*>(g_part + (t * 2 + 1) * (size_t)H_DIM + h);
        uint4 o;
        o.x = f2tf32(fmaxf(0.5f * (a.x + b.x), 0.f));
        o.y = f2tf32(fmaxf(0.5f * (a.y + b.y), 0.f));
        o.z = f2tf32(fmaxf(0.5f * (a.z + b.z), 0.f));
        o.w = f2tf32(fmaxf(0.5f * (a.w + b.w), 0.f));
        *reinterpret_cast<uint4*>(g_act + t * (size_t)H_DIM + h) = o;
    }
}

// ---------------------------------------------------------------------------
// Condense GEMM + bias + residual: M=128, N=128, K=4096.
// grid: (D/128 = 8, T/128 = 128)
// ---------------------------------------------------------------------------
__global__ __launch_bounds__(256, 2) void condense_tc(
    const float* __restrict__ bc, const float* __restrict__ seq,
    float* __restrict__ out)
{
    const int mt = blockIdx.y, nt = blockIdx.x;
    const int m0 = mt * 128, n0 = nt * 128;

    extern __shared__ char smem[];
    const uint32_t sb = smem_u32(smem);
    const int tid = threadIdx.x;

    const int ra = tid >> 1;
    const float* aSrc = g_act + (size_t)(m0 + ra) * H_DIM;
    const float* bSrc = g_Wc + (size_t)(n0 + ra) * H_DIM;

    gemm_core(smem, sb, aSrc, 16u, bSrc, H_DIM / 32);

    const float* Cs = (const float*)(smem + SM_CS);
    const int r = tid >> 1, ch = (tid & 1) * 64;
    const int t = m0 + r;
    const size_t base = (size_t)t * D_DIM + n0 + ch;
    const float* cp = Cs + r * LDC + ch;
    #pragma unroll
    for (int j = 0; j < 64; j += 4) {
        float4 cv = *reinterpret_cast<const float4*>(bc + n0 + ch + j);
        float4 rv = *reinterpret_cast<const float4*>(seq + base + j);
        float4 o;
        o.x = cp[j + 0] + cv.x + rv.x;
        o.y = cp[j + 1] + cv.y + rv.y;
        o.z = cp[j + 2] + cv.z + rv.z;
        o.w = cp[j + 3] + cv.w + rv.w;
        *reinterpret_cast<float4*>(out + base + j) = o;
    }
}

// ---------------------------------------------------------------------------
extern "C" void kernel_launch(void* const* d_in, const int* in_sizes, int n_in,
                              void* d_out, int out_size)
{
    const float* seq   = (const float*)d_in[0];
    const float* gamma = (const float*)d_in[1];
    const float* beta  = (const float*)d_in[2];
    const float* Wg    = (const float*)d_in[3];
    const float* bg    = (const float*)d_in[4];
    const float* We    = (const float*)d_in[5];
    const float* be    = (const float*)d_in[6];
    const float* Wc    = (const float*)d_in[7];
    const float* bc    = (const float*)d_in[8];
    float* out = (float*)d_out;

    cudaFuncSetAttribute(expert_tc, cudaFuncAttributeMaxDynamicSharedMemorySize, SMEM_BYTES);
    cudaFuncSetAttribute(condense_tc, cudaFuncAttributeMaxDynamicSharedMemorySize, SMEM_BYTES);

    float* gWe; cudaGetSymbolAddress((void**)&gWe, g_We);
    float* gWc; cudaGetSymbolAddress((void**)&gWc, g_Wc);

    zero_cnt_kernel<<<1, 32>>>();
    cvt_kernel<<<4096, 256>>>(We, gWe, E_NUM * H_DIM * D_DIM / 4);
    cvt_kernel<<<1024, 256>>>(Wc, gWc, D_DIM * H_DIM / 4);
    ln_gate_kernel<<<T_TOK, 256>>>(seq, gamma, beta, Wg, bg);
    {
        dim3 grid(H_DIM / 128, T_TOK / 128, E_NUM);
        expert_tc<<<grid, 256, SMEM_BYTES>>>(be);
    }
    relu_combine_kernel<<<4096, 256>>>();
    {
        dim3 grid(D_DIM / 128, T_TOK / 128);
        condense_tc<<<grid, 256, SMEM_BYTES>>>(bc, seq, out);
    }
}